// round 2
// baseline (speedup 1.0000x reference)
#include <cuda_runtime.h>
#include <math.h>

#define B_  512
#define T_  128
#define V_  59
#define H_  512
#define H3_ 1536
#define BT_ (B_*T_)

// ---------------- scratch (static __device__, no allocations) ----------------
__device__ float g_gif[(size_t)BT_*H3_];   // forward  gi (includes bih)
__device__ float g_gib[(size_t)BT_*H3_];   // backward gi (includes bih)
__device__ float g_hf [(size_t)BT_*H_];    // forward  pre-update hiddens
__device__ float g_hb [(size_t)BT_*H_];    // backward pre-update hiddens (time-aligned)
__device__ float g_num[T_];
__device__ float g_den[T_];

// ---------------- init: zero h0 states and loss accumulators ----------------
__global__ void k_init() {
    int idx = blockIdx.x * 256 + threadIdx.x;
    if (idx < B_*H_) {
        int b = idx >> 9, j = idx & 511;
        g_hf[(size_t)b*T_*H_ + j] = 0.f;                       // hf[b,0,:]   = 0
        g_hb[(size_t)b*T_*H_ + (size_t)(T_-1)*H_ + j] = 0.f;   // hb[b,T-1,:] = 0
    }
    if (idx < T_) { g_num[idx] = 0.f; g_den[idx] = 0.f; }
}

// ---------------- phase 1: fused gi GEMM for both directions ----------------
// rows = bt (B*T), cols = 3H. accA shares the [values;masks] K=118 part between
// directions; accF/accB add the delta parts (same Wd columns 118..176 of Wih).
__global__ __launch_bounds__(256) void k_phase1(
    const float* __restrict__ values, const float* __restrict__ masks,
    const float* __restrict__ df,     const float* __restrict__ db,
    const float* __restrict__ Wih,    const float* __restrict__ bih)
{
    __shared__ float sx [64][33];
    __shared__ float sx2[64][33];
    __shared__ float sw [64][33];

    int tid = threadIdx.x;
    int tx = tid & 15, ty = tid >> 4;
    int rBase = blockIdx.y * 64;   // bt rows
    int cBase = blockIdx.x * 64;   // output cols (0..1535)

    float accA[4][4]; float accF[4][4]; float accB[4][4];
    #pragma unroll
    for (int i = 0; i < 4; i++)
        #pragma unroll
        for (int j = 0; j < 4; j++) { accA[i][j]=0.f; accF[i][j]=0.f; accB[i][j]=0.f; }

    // ---- part A: k in [0,118)  (values | masks), zero-padded to 128 ----
    for (int k0 = 0; k0 < 118; k0 += 32) {
        for (int l = tid; l < 64*32; l += 256) {
            int r = l >> 5, kk = l & 31;
            int k = k0 + kk;
            int bt = rBase + r;
            float xv = 0.f;
            if (k < 59)       xv = values[(size_t)bt*V_ + k];
            else if (k < 118) xv = masks [(size_t)bt*V_ + (k - 59)];
            sx[r][kk] = xv;
        }
        for (int l = tid; l < 64*32; l += 256) {
            int r = l >> 5, kk = l & 31;
            int k = k0 + kk;
            sw[r][kk] = (k < 118) ? Wih[(size_t)(cBase + r)*177 + k] : 0.f;
        }
        __syncthreads();
        #pragma unroll
        for (int kk = 0; kk < 32; kk++) {
            float xr[4], wr[4];
            #pragma unroll
            for (int i = 0; i < 4; i++) xr[i] = sx[ty + 16*i][kk];
            #pragma unroll
            for (int j = 0; j < 4; j++) wr[j] = sw[tx + 16*j][kk];
            #pragma unroll
            for (int i = 0; i < 4; i++)
                #pragma unroll
                for (int j = 0; j < 4; j++) accA[i][j] += xr[i]*wr[j];
        }
        __syncthreads();
    }

    // ---- part F/B: k in [0,59) against Wd = Wih[:,118:177] ----
    for (int k0 = 0; k0 < 59; k0 += 32) {
        for (int l = tid; l < 64*32; l += 256) {
            int r = l >> 5, kk = l & 31;
            int k = k0 + kk;
            int bt = rBase + r;
            int b = bt >> 7, t = bt & 127;
            int btf = (b << 7) + (127 - t);
            float fv = 0.f, bv = 0.f;
            if (k < 59) {
                fv = df[(size_t)bt *V_ + k];
                bv = db[(size_t)btf*V_ + k];
            }
            sx [r][kk] = fv;
            sx2[r][kk] = bv;
        }
        for (int l = tid; l < 64*32; l += 256) {
            int r = l >> 5, kk = l & 31;
            int k = k0 + kk;
            sw[r][kk] = (k < 59) ? Wih[(size_t)(cBase + r)*177 + 118 + k] : 0.f;
        }
        __syncthreads();
        #pragma unroll
        for (int kk = 0; kk < 32; kk++) {
            float fr[4], br[4], wr[4];
            #pragma unroll
            for (int i = 0; i < 4; i++) { fr[i] = sx[ty+16*i][kk]; br[i] = sx2[ty+16*i][kk]; }
            #pragma unroll
            for (int j = 0; j < 4; j++) wr[j] = sw[tx + 16*j][kk];
            #pragma unroll
            for (int i = 0; i < 4; i++)
                #pragma unroll
                for (int j = 0; j < 4; j++) {
                    accF[i][j] += fr[i]*wr[j];
                    accB[i][j] += br[i]*wr[j];
                }
        }
        __syncthreads();
    }

    // ---- write: gif[bt,c] and gib[b, T-1-t, c] ----
    #pragma unroll
    for (int j = 0; j < 4; j++) {
        int c = cBase + tx + 16*j;
        float bias = bih[c];
        #pragma unroll
        for (int i = 0; i < 4; i++) {
            int bt = rBase + ty + 16*i;
            int b = bt >> 7, t = bt & 127;
            int btf = (b << 7) + (127 - t);
            g_gif[(size_t)bt *H3_ + c] = accA[i][j] + accF[i][j] + bias;
            g_gib[(size_t)btf*H3_ + c] = accA[i][j] + accB[i][j] + bias;
        }
    }
}

// ---------------- phase 2: one recurrence step, both directions ----------------
// grid (8 jblk, 8 bblk, 2 dir). CTA tile: 64 b x 64 j x 3 gates, K=512.
__global__ __launch_bounds__(256) void k_gru_step(
    const float* __restrict__ Whh, const float* __restrict__ bhh, int s)
{
    int dir = blockIdx.z;
    const float* gi = dir ? g_gib : g_gif;
    float* hbuf     = dir ? g_hb  : g_hf;
    int t_in  = dir ? (127 - s) : s;
    int t_out = dir ? (126 - s) : (s + 1);

    __shared__ float sh [64][33];
    __shared__ float swm[3][64][33];

    int tid = threadIdx.x;
    int tx = tid & 15, ty = tid >> 4;
    int bBase = blockIdx.y * 64;
    int jBase = blockIdx.x * 64;

    float acc[3][4][4];
    #pragma unroll
    for (int g = 0; g < 3; g++)
        #pragma unroll
        for (int i = 0; i < 4; i++)
            #pragma unroll
            for (int j = 0; j < 4; j++) acc[g][i][j] = 0.f;

    for (int k0 = 0; k0 < H_; k0 += 32) {
        // h tile: 64 rows x 32 k (vectorized global loads)
        for (int l = tid; l < 64*8; l += 256) {
            int r = l >> 3, q = l & 7;
            float4 v = *reinterpret_cast<const float4*>(
                &hbuf[((size_t)(bBase + r)*T_ + t_in)*H_ + k0 + q*4]);
            sh[r][q*4+0] = v.x; sh[r][q*4+1] = v.y;
            sh[r][q*4+2] = v.z; sh[r][q*4+3] = v.w;
        }
        // Whh tiles for 3 gates: rows g*H + jBase + r
        for (int l = tid; l < 3*64*8; l += 256) {
            int g = l / (64*8); int rem = l - g*(64*8);
            int r = rem >> 3, q = rem & 7;
            float4 v = *reinterpret_cast<const float4*>(
                &Whh[(size_t)(g*H_ + jBase + r)*H_ + k0 + q*4]);
            swm[g][r][q*4+0] = v.x; swm[g][r][q*4+1] = v.y;
            swm[g][r][q*4+2] = v.z; swm[g][r][q*4+3] = v.w;
        }
        __syncthreads();
        #pragma unroll
        for (int kk = 0; kk < 32; kk++) {
            float hr[4];
            #pragma unroll
            for (int i = 0; i < 4; i++) hr[i] = sh[ty + 16*i][kk];
            #pragma unroll
            for (int g = 0; g < 3; g++) {
                float wr[4];
                #pragma unroll
                for (int j = 0; j < 4; j++) wr[j] = swm[g][tx + 16*j][kk];
                #pragma unroll
                for (int i = 0; i < 4; i++)
                    #pragma unroll
                    for (int j = 0; j < 4; j++) acc[g][i][j] += hr[i]*wr[j];
            }
        }
        __syncthreads();
    }

    // gate epilogue
    #pragma unroll
    for (int i = 0; i < 4; i++) {
        int b = bBase + ty + 16*i;
        const float* girow = &gi[((size_t)b*T_ + s)*H3_];
        #pragma unroll
        for (int j = 0; j < 4; j++) {
            int jj = jBase + tx + 16*j;
            float ghr = acc[0][i][j] + bhh[jj];
            float ghz = acc[1][i][j] + bhh[H_  + jj];
            float ghn = acc[2][i][j] + bhh[2*H_ + jj];
            float r = 1.f / (1.f + __expf(-(girow[jj]        + ghr)));
            float z = 1.f / (1.f + __expf(-(girow[H_  + jj]  + ghz)));
            float n = tanhf(girow[2*H_ + jj] + r*ghn);
            float hp = hbuf[((size_t)b*T_ + t_in )*H_ + jj];
            hbuf[((size_t)b*T_ + t_out)*H_ + jj] = (1.f - z)*n + z*hp;
        }
    }
}

// ---------------- phase 3: fused regression chain + loss ----------------
// grid (T, B/16). CTA: 16 batches at one t. Dynamic smem (> 48 KB).
#define P3_WBIG  0                       // [59][237]  Wf|Wc|Wi rows
#define P3_W     (P3_WBIG + 59*237)      // [59][33]   Wh k-tile
#define P3_H     (P3_W    + 59*33)       // [16][33]   h2 k-tile
#define P3_XV    (P3_H    + 16*33)       // [16][60]
#define P3_VAL   (P3_XV   + 16*60)
#define P3_MSK   (P3_VAL  + 16*60)
#define P3_XH    (P3_MSK  + 16*60)
#define P3_RED   (P3_XH   + 16*60)       // [256]
#define P3_TOTAL (P3_RED  + 256)         // floats

__global__ __launch_bounds__(256) void k_post(
    const float* __restrict__ values, const float* __restrict__ masks,
    const float* __restrict__ Wh, const float* __restrict__ bh,
    const float* __restrict__ Wf, const float* __restrict__ bf,
    const float* __restrict__ Wc, const float* __restrict__ bc,
    const float* __restrict__ Wi, const float* __restrict__ bi,
    float* __restrict__ out)
{
    extern __shared__ float smem[];
    float* s_wbig = smem + P3_WBIG;
    float* s_w    = smem + P3_W;
    float* s_h    = smem + P3_H;
    float* s_xv   = smem + P3_XV;
    float* s_val  = smem + P3_VAL;
    float* s_msk  = smem + P3_MSK;
    float* s_xh   = smem + P3_XH;
    float* s_red  = smem + P3_RED;

    int t = blockIdx.x;
    int bBase = blockIdx.y * 16;
    int tid = threadIdx.x;
    int v   = tid & 63;
    int grp = tid >> 6;

    // stage small weight matrices: row v = [Wf(59) | Wc(118) | Wi(59)]
    for (int l = tid; l < 59*236; l += 256) {
        int r = l / 236, c = l - r*236;
        float w;
        if (c < 59)       w = Wf[r*59 + c];
        else if (c < 177) w = Wc[r*118 + (c - 59)];
        else              w = Wi[r*59 + (c - 177)];
        s_wbig[r*237 + c] = w;
    }

    // ---- x_v = [hf,hb] @ Wh^T + bh  (K=1024, tiled by 32) ----
    float acc[4] = {0.f, 0.f, 0.f, 0.f};
    for (int k0 = 0; k0 < 1024; k0 += 32) {
        for (int l = tid; l < 59*32; l += 256) {
            int r = l >> 5, kk = l & 31;
            s_w[r*33 + kk] = Wh[(size_t)r*1024 + k0 + kk];
        }
        for (int l = tid; l < 16*32; l += 256) {
            int r = l >> 5, kk = l & 31;
            int k = k0 + kk;
            int b = bBase + r;
            float hv = (k < 512)
                ? g_hf[((size_t)b*T_ + t)*H_ + k]
                : g_hb[((size_t)b*T_ + t)*H_ + (k - 512)];
            s_h[r*33 + kk] = hv;
        }
        __syncthreads();
        if (v < 59) {
            #pragma unroll
            for (int kk = 0; kk < 32; kk++) {
                float w = s_w[v*33 + kk];
                #pragma unroll
                for (int i = 0; i < 4; i++) acc[i] += w * s_h[(grp*4 + i)*33 + kk];
            }
        }
        __syncthreads();
    }
    if (v < 59) {
        float bias = bh[v];
        #pragma unroll
        for (int i = 0; i < 4; i++) s_xv[(grp*4 + i)*60 + v] = acc[i] + bias;
    }
    // values / masks
    for (int l = tid; l < 16*59; l += 256) {
        int r = l / 59, kk = l - r*59;
        size_t g = ((size_t)(bBase + r)*T_ + t)*V_ + kk;
        s_val[r*60 + kk] = values[g];
        s_msk[r*60 + kk] = masks [g];
    }
    __syncthreads();

    // ---- x_h = feat_reg(values) + combine([x_v, masks]) ----
    if (v < 59) {
        float xh[4];
        float bias = bf[v] + bc[v];
        #pragma unroll
        for (int i = 0; i < 4; i++) xh[i] = bias;
        for (int k = 0; k < 59; k++) {
            float wf  = (k == v) ? 0.f : s_wbig[v*237 + k];
            float wc1 = s_wbig[v*237 + 59 + k];
            float wc2 = s_wbig[v*237 + 118 + k];
            #pragma unroll
            for (int i = 0; i < 4; i++) {
                int r = grp*4 + i;
                xh[i] += s_val[r*60 + k]*wf + s_xv[r*60 + k]*wc1 + s_msk[r*60 + k]*wc2;
            }
        }
        #pragma unroll
        for (int i = 0; i < 4; i++) s_xh[(grp*4 + i)*60 + v] = xh[i];
    }
    __syncthreads();

    // ---- imp, x_imp output, loss contributions ----
    float lnum = 0.f, lden = 0.f;
    if (v < 59) {
        #pragma unroll
        for (int i = 0; i < 4; i++) {
            int r = grp*4 + i;
            int b = bBase + r;
            float imp = bi[v];
            for (int k = 0; k < 59; k++) imp += s_xh[r*60 + k] * s_wbig[v*237 + 177 + k];
            float val = s_val[r*60 + v], m = s_msk[r*60 + v];
            out[((size_t)b*T_ + t)*V_ + v] = m*val + (1.f - m)*imp;
            lnum += fabsf(val - imp) * m;
            lden += m;
        }
    }
    // block reduce num/den -> atomics per t
    s_red[tid] = lnum; __syncthreads();
    for (int st = 128; st > 0; st >>= 1) { if (tid < st) s_red[tid] += s_red[tid + st]; __syncthreads(); }
    if (tid == 0) atomicAdd(&g_num[t], s_red[0]);
    __syncthreads();
    s_red[tid] = lden; __syncthreads();
    for (int st = 128; st > 0; st >>= 1) { if (tid < st) s_red[tid] += s_red[tid + st]; __syncthreads(); }
    if (tid == 0) atomicAdd(&g_den[t], s_red[0]);
}

// ---------------- final loss reduction ----------------
__global__ void k_loss(float* __restrict__ out) {
    __shared__ float sr[128];
    int t = threadIdx.x;
    sr[t] = g_num[t] / (g_den[t] + 1e-5f);
    __syncthreads();
    for (int s = 64; s > 0; s >>= 1) { if (t < s) sr[t] += sr[t + s]; __syncthreads(); }
    if (t == 0) out[(size_t)B_*T_*V_] = sr[0];
}

// ---------------- launch ----------------
extern "C" void kernel_launch(void* const* d_in, const int* in_sizes, int n_in,
                              void* d_out, int out_size) {
    const float* values = (const float*)d_in[0];
    const float* masks  = (const float*)d_in[1];
    const float* df     = (const float*)d_in[2];
    const float* db     = (const float*)d_in[3];
    const float* Wih    = (const float*)d_in[4];
    const float* Whh    = (const float*)d_in[5];
    const float* bih    = (const float*)d_in[6];
    const float* bhh    = (const float*)d_in[7];
    const float* Wh     = (const float*)d_in[8];
    const float* bh     = (const float*)d_in[9];
    const float* Wf     = (const float*)d_in[10];
    const float* bf     = (const float*)d_in[11];
    const float* Wc     = (const float*)d_in[12];
    const float* bc     = (const float*)d_in[13];
    const float* Wi     = (const float*)d_in[14];
    const float* bi     = (const float*)d_in[15];
    float* out = (float*)d_out;

    cudaFuncSetAttribute(k_post, cudaFuncAttributeMaxDynamicSharedMemorySize,
                         P3_TOTAL * (int)sizeof(float));

    k_init<<<(B_*H_ + 255)/256, 256>>>();
    k_phase1<<<dim3(H3_/64, BT_/64), 256>>>(values, masks, df, db, Wih, bih);
    for (int s = 0; s < T_ - 1; s++)
        k_gru_step<<<dim3(8, 8, 2), 256>>>(Whh, bhh, s);
    k_post<<<dim3(T_, B_/16), 256, P3_TOTAL * sizeof(float)>>>(
        values, masks, Wh, bh, Wf, bf, Wc, bc, Wi, bi, out);
    k_loss<<<1, 128>>>(out);
}

// round 5
// speedup vs baseline: 1.3786x; 1.3786x over previous
#include <cuda_runtime.h>
#include <math.h>

#define B_  512
#define T_  128
#define V_  59
#define H_  512
#define H3_ 1536
#define BT_ (B_*T_)

// ---------------- scratch (static __device__, no allocations) ----------------
__device__ float g_gif[(size_t)BT_*H3_];   // forward  gi (includes bih)
__device__ float g_gib[(size_t)BT_*H3_];   // backward gi (includes bih)
__device__ float g_hf [(size_t)BT_*H_];    // forward  pre-update hiddens
__device__ float g_hb [(size_t)BT_*H_];    // backward pre-update hiddens (time-aligned)
__device__ float g_num[T_];
__device__ float g_den[T_];

// ---------------- f32x2 helpers (Blackwell packed fp32) ----------------
typedef unsigned long long ull;
__device__ __forceinline__ ull pk2(float a, float b) {
    ull r; asm("mov.b64 %0, {%1, %2};" : "=l"(r) : "f"(a), "f"(b)); return r;
}
__device__ __forceinline__ void upk2(ull v, float& a, float& b) {
    asm("mov.b64 {%0, %1}, %2;" : "=f"(a), "=f"(b) : "l"(v));
}
__device__ __forceinline__ void fma2(ull& d, ull a, ull b) {
    asm("fma.rn.f32x2 %0, %1, %2, %3;" : "=l"(d) : "l"(a), "l"(b), "l"(d));
}

// ---------------- init: zero h0 states and loss accumulators ----------------
__global__ void k_init() {
    int idx = blockIdx.x * 256 + threadIdx.x;
    if (idx < B_*H_) {
        int b = idx >> 9, j = idx & 511;
        g_hf[(size_t)b*T_*H_ + j] = 0.f;                       // hf[b,0,:]   = 0
        g_hb[(size_t)b*T_*H_ + (size_t)(T_-1)*H_ + j] = 0.f;   // hb[b,T-1,:] = 0
    }
    if (idx < T_) { g_num[idx] = 0.f; g_den[idx] = 0.f; }
}

// ---------------- phase 1: fused gi GEMM for both directions ----------------
__global__ __launch_bounds__(256) void k_phase1(
    const float* __restrict__ values, const float* __restrict__ masks,
    const float* __restrict__ df,     const float* __restrict__ db,
    const float* __restrict__ Wih,    const float* __restrict__ bih)
{
    __shared__ float sx [64][33];
    __shared__ float sx2[64][33];
    __shared__ float sw [64][33];

    int tid = threadIdx.x;
    int tx = tid & 15, ty = tid >> 4;
    int rBase = blockIdx.y * 64;   // bt rows
    int cBase = blockIdx.x * 64;   // output cols (0..1535)

    float accA[4][4]; float accF[4][4]; float accB[4][4];
    #pragma unroll
    for (int i = 0; i < 4; i++)
        #pragma unroll
        for (int j = 0; j < 4; j++) { accA[i][j]=0.f; accF[i][j]=0.f; accB[i][j]=0.f; }

    // ---- part A: k in [0,118)  (values | masks), zero-padded ----
    for (int k0 = 0; k0 < 118; k0 += 32) {
        for (int l = tid; l < 64*32; l += 256) {
            int r = l >> 5, kk = l & 31;
            int k = k0 + kk;
            int bt = rBase + r;
            float xv = 0.f;
            if (k < 59)       xv = values[(size_t)bt*V_ + k];
            else if (k < 118) xv = masks [(size_t)bt*V_ + (k - 59)];
            sx[r][kk] = xv;
        }
        for (int l = tid; l < 64*32; l += 256) {
            int r = l >> 5, kk = l & 31;
            int k = k0 + kk;
            sw[r][kk] = (k < 118) ? Wih[(size_t)(cBase + r)*177 + k] : 0.f;
        }
        __syncthreads();
        #pragma unroll
        for (int kk = 0; kk < 32; kk++) {
            float xr[4], wr[4];
            #pragma unroll
            for (int i = 0; i < 4; i++) xr[i] = sx[ty + 16*i][kk];
            #pragma unroll
            for (int j = 0; j < 4; j++) wr[j] = sw[tx + 16*j][kk];
            #pragma unroll
            for (int i = 0; i < 4; i++)
                #pragma unroll
                for (int j = 0; j < 4; j++) accA[i][j] += xr[i]*wr[j];
        }
        __syncthreads();
    }

    // ---- part F/B: k in [0,59) against Wd = Wih[:,118:177] ----
    for (int k0 = 0; k0 < 59; k0 += 32) {
        for (int l = tid; l < 64*32; l += 256) {
            int r = l >> 5, kk = l & 31;
            int k = k0 + kk;
            int bt = rBase + r;
            int b = bt >> 7, t = bt & 127;
            int btf = (b << 7) + (127 - t);
            float fv = 0.f, bv = 0.f;
            if (k < 59) {
                fv = df[(size_t)bt *V_ + k];
                bv = db[(size_t)btf*V_ + k];
            }
            sx [r][kk] = fv;
            sx2[r][kk] = bv;
        }
        for (int l = tid; l < 64*32; l += 256) {
            int r = l >> 5, kk = l & 31;
            int k = k0 + kk;
            sw[r][kk] = (k < 59) ? Wih[(size_t)(cBase + r)*177 + 118 + k] : 0.f;
        }
        __syncthreads();
        #pragma unroll
        for (int kk = 0; kk < 32; kk++) {
            float fr[4], br[4], wr[4];
            #pragma unroll
            for (int i = 0; i < 4; i++) { fr[i] = sx[ty+16*i][kk]; br[i] = sx2[ty+16*i][kk]; }
            #pragma unroll
            for (int j = 0; j < 4; j++) wr[j] = sw[tx + 16*j][kk];
            #pragma unroll
            for (int i = 0; i < 4; i++)
                #pragma unroll
                for (int j = 0; j < 4; j++) {
                    accF[i][j] += fr[i]*wr[j];
                    accB[i][j] += br[i]*wr[j];
                }
        }
        __syncthreads();
    }

    // ---- write: gif[bt,c] and gib[b, T-1-t, c] ----
    #pragma unroll
    for (int j = 0; j < 4; j++) {
        int c = cBase + tx + 16*j;
        float bias = bih[c];
        #pragma unroll
        for (int i = 0; i < 4; i++) {
            int bt = rBase + ty + 16*i;
            int b = bt >> 7, t = bt & 127;
            int btf = (b << 7) + (127 - t);
            g_gif[(size_t)bt *H3_ + c] = accA[i][j] + accF[i][j] + bias;
            g_gib[(size_t)btf*H3_ + c] = accA[i][j] + accB[i][j] + bias;
        }
    }
}

// ---------------- phase 2: one recurrence step, both directions ----------------
// grid (8 jblk, 8 bblk, 2 dir). CTA tile: 64 b x 64 j x 3 gates, K=512.
// FFMA2 mainloop (fma.rn.f32x2), single-sync double-buffered smem.
// smem layout per buffer:
//   h tile: [64][33] floats          (2112 floats)
//   w tile: 3 gates x [32][66] (transposed: row=kk, col=j)  (3*2112 floats)
#define SP_H   33
#define SP_W   66
#define HBF    (64*SP_H)                 // 2112
#define WBF    (32*SP_W)                 // 2112
#define BUF_F  (HBF + 3*WBF)             // 8448 floats per buffer
#define STEP_SMEM (2*BUF_F*(int)sizeof(float))

__global__ __launch_bounds__(256) void k_gru_step(
    const float* __restrict__ Whh, const float* __restrict__ bhh, int s)
{
    extern __shared__ float smem[];

    int dir = blockIdx.z;
    const float* gi = dir ? g_gib : g_gif;
    float* hbuf     = dir ? g_hb  : g_hf;
    int t_in  = dir ? (127 - s) : s;
    int t_out = dir ? (126 - s) : (s + 1);

    int tid = threadIdx.x;
    int tx = tid & 15, ty = tid >> 4;
    int bBase = blockIdx.y * 64;
    int jBase = blockIdx.x * 64;

    // accumulators: [gate][i][jpair], each ull = 2 adjacent output cols
    ull acc[3][4][2];
    #pragma unroll
    for (int g = 0; g < 3; g++)
        #pragma unroll
        for (int i = 0; i < 4; i++)
            #pragma unroll
            for (int jp = 0; jp < 2; jp++) acc[g][i][jp] = 0ull;

    // indices for cooperative loads
    // h: 2 float4 per thread; w: 6 float4 per thread
    int hl0 = tid, hl1 = tid + 256;
    int hr0 = hl0 >> 3, hq0 = hl0 & 7;
    int hr1 = hl1 >> 3, hq1 = hl1 & 7;

    // ---- prologue: load k-tile 0 and store to buffer 0 ----
    {
        float4 ph0 = *reinterpret_cast<const float4*>(
            &hbuf[((size_t)(bBase + hr0)*T_ + t_in)*H_ + hq0*4]);
        float4 ph1 = *reinterpret_cast<const float4*>(
            &hbuf[((size_t)(bBase + hr1)*T_ + t_in)*H_ + hq1*4]);
        float4 pw[6];
        #pragma unroll
        for (int u = 0; u < 6; u++) {
            int l = tid + u*256;
            int g = l >> 9, rem = l & 511;
            int r = rem >> 3, q = rem & 7;
            pw[u] = *reinterpret_cast<const float4*>(
                &Whh[(size_t)(g*H_ + jBase + r)*H_ + q*4]);
        }
        float* bh = smem;
        bh[hr0*SP_H + hq0*4+0] = ph0.x; bh[hr0*SP_H + hq0*4+1] = ph0.y;
        bh[hr0*SP_H + hq0*4+2] = ph0.z; bh[hr0*SP_H + hq0*4+3] = ph0.w;
        bh[hr1*SP_H + hq1*4+0] = ph1.x; bh[hr1*SP_H + hq1*4+1] = ph1.y;
        bh[hr1*SP_H + hq1*4+2] = ph1.z; bh[hr1*SP_H + hq1*4+3] = ph1.w;
        #pragma unroll
        for (int u = 0; u < 6; u++) {
            int l = tid + u*256;
            int g = l >> 9, rem = l & 511;
            int r = rem >> 3, q = rem & 7;
            float* bw = smem + HBF + g*WBF;
            bw[(q*4+0)*SP_W + r] = pw[u].x;
            bw[(q*4+1)*SP_W + r] = pw[u].y;
            bw[(q*4+2)*SP_W + r] = pw[u].z;
            bw[(q*4+3)*SP_W + r] = pw[u].w;
        }
    }
    __syncthreads();

    // ---- mainloop over 16 k-tiles ----
    for (int kt = 0; kt < 16; kt++) {
        int cur = kt & 1;
        float* buf = smem + cur*BUF_F;

        // prefetch next tile into registers
        float4 ph0, ph1, pw[6];
        if (kt < 15) {
            int k0 = (kt + 1) * 32;
            ph0 = *reinterpret_cast<const float4*>(
                &hbuf[((size_t)(bBase + hr0)*T_ + t_in)*H_ + k0 + hq0*4]);
            ph1 = *reinterpret_cast<const float4*>(
                &hbuf[((size_t)(bBase + hr1)*T_ + t_in)*H_ + k0 + hq1*4]);
            #pragma unroll
            for (int u = 0; u < 6; u++) {
                int l = tid + u*256;
                int g = l >> 9, rem = l & 511;
                int r = rem >> 3, q = rem & 7;
                pw[u] = *reinterpret_cast<const float4*>(
                    &Whh[(size_t)(g*H_ + jBase + r)*H_ + k0 + q*4]);
            }
        }

        // compute on current buffer
        const float* bh = buf;
        const float* bw0 = buf + HBF;
        const float* bw1 = buf + HBF + WBF;
        const float* bw2 = buf + HBF + 2*WBF;
        #pragma unroll
        for (int kk = 0; kk < 32; kk++) {
            ull h2[4];
            #pragma unroll
            for (int i = 0; i < 4; i++) {
                float hv = bh[(ty + 16*i)*SP_H + kk];
                h2[i] = pk2(hv, hv);
            }
            ull w00 = *reinterpret_cast<const ull*>(&bw0[kk*SP_W + 2*tx]);
            ull w01 = *reinterpret_cast<const ull*>(&bw0[kk*SP_W + 32 + 2*tx]);
            ull w10 = *reinterpret_cast<const ull*>(&bw1[kk*SP_W + 2*tx]);
            ull w11 = *reinterpret_cast<const ull*>(&bw1[kk*SP_W + 32 + 2*tx]);
            ull w20 = *reinterpret_cast<const ull*>(&bw2[kk*SP_W + 2*tx]);
            ull w21 = *reinterpret_cast<const ull*>(&bw2[kk*SP_W + 32 + 2*tx]);
            #pragma unroll
            for (int i = 0; i < 4; i++) {
                fma2(acc[0][i][0], h2[i], w00);
                fma2(acc[0][i][1], h2[i], w01);
                fma2(acc[1][i][0], h2[i], w10);
                fma2(acc[1][i][1], h2[i], w11);
                fma2(acc[2][i][0], h2[i], w20);
                fma2(acc[2][i][1], h2[i], w21);
            }
        }

        // store prefetched tile into the other buffer
        if (kt < 15) {
            float* nbuf = smem + (1 - cur)*BUF_F;
            float* bhn = nbuf;
            bhn[hr0*SP_H + hq0*4+0] = ph0.x; bhn[hr0*SP_H + hq0*4+1] = ph0.y;
            bhn[hr0*SP_H + hq0*4+2] = ph0.z; bhn[hr0*SP_H + hq0*4+3] = ph0.w;
            bhn[hr1*SP_H + hq1*4+0] = ph1.x; bhn[hr1*SP_H + hq1*4+1] = ph1.y;
            bhn[hr1*SP_H + hq1*4+2] = ph1.z; bhn[hr1*SP_H + hq1*4+3] = ph1.w;
            #pragma unroll
            for (int u = 0; u < 6; u++) {
                int l = tid + u*256;
                int g = l >> 9, rem = l & 511;
                int r = rem >> 3, q = rem & 7;
                float* bwn = nbuf + HBF + g*WBF;
                bwn[(q*4+0)*SP_W + r] = pw[u].x;
                bwn[(q*4+1)*SP_W + r] = pw[u].y;
                bwn[(q*4+2)*SP_W + r] = pw[u].z;
                bwn[(q*4+3)*SP_W + r] = pw[u].w;
            }
        }
        __syncthreads();
    }

    // ---- gate epilogue ----
    #pragma unroll
    for (int i = 0; i < 4; i++) {
        int b = bBase + ty + 16*i;
        const float* girow = &gi[((size_t)b*T_ + s)*H3_];
        const float* hprow = &hbuf[((size_t)b*T_ + t_in )*H_];
        float*       horow = &hbuf[((size_t)b*T_ + t_out)*H_];
        #pragma unroll
        for (int jp = 0; jp < 2; jp++) {
            int c0 = jBase + jp*32 + 2*tx;
            float gr[2], gz[2], gn[2];
            upk2(acc[0][i][jp], gr[0], gr[1]);
            upk2(acc[1][i][jp], gz[0], gz[1]);
            upk2(acc[2][i][jp], gn[0], gn[1]);
            #pragma unroll
            for (int u = 0; u < 2; u++) {
                int jj = c0 + u;
                float ghr = gr[u] + bhh[jj];
                float ghz = gz[u] + bhh[H_  + jj];
                float ghn = gn[u] + bhh[2*H_ + jj];
                float r = 1.f / (1.f + __expf(-(girow[jj]        + ghr)));
                float z = 1.f / (1.f + __expf(-(girow[H_  + jj]  + ghz)));
                float n = tanhf(girow[2*H_ + jj] + r*ghn);
                float hp = hprow[jj];
                horow[jj] = (1.f - z)*n + z*hp;
            }
        }
    }
}

// ---------------- phase 3: fused regression chain + loss ----------------
#define P3_WBIG  0                       // [59][237]  Wf|Wc|Wi rows
#define P3_W     (P3_WBIG + 59*237)      // [59][33]   Wh k-tile
#define P3_H     (P3_W    + 59*33)       // [16][33]   h2 k-tile
#define P3_XV    (P3_H    + 16*33)       // [16][60]
#define P3_VAL   (P3_XV   + 16*60)
#define P3_MSK   (P3_VAL  + 16*60)
#define P3_XH    (P3_MSK  + 16*60)
#define P3_RED   (P3_XH   + 16*60)       // [256]
#define P3_TOTAL (P3_RED  + 256)         // floats

__global__ __launch_bounds__(256) void k_post(
    const float* __restrict__ values, const float* __restrict__ masks,
    const float* __restrict__ Wh, const float* __restrict__ bh,
    const float* __restrict__ Wf, const float* __restrict__ bf,
    const float* __restrict__ Wc, const float* __restrict__ bc,
    const float* __restrict__ Wi, const float* __restrict__ bi,
    float* __restrict__ out)
{
    extern __shared__ float smem[];
    float* s_wbig = smem + P3_WBIG;
    float* s_w    = smem + P3_W;
    float* s_h    = smem + P3_H;
    float* s_xv   = smem + P3_XV;
    float* s_val  = smem + P3_VAL;
    float* s_msk  = smem + P3_MSK;
    float* s_xh   = smem + P3_XH;
    float* s_red  = smem + P3_RED;

    int t = blockIdx.x;
    int bBase = blockIdx.y * 16;
    int tid = threadIdx.x;
    int v   = tid & 63;
    int grp = tid >> 6;

    for (int l = tid; l < 59*236; l += 256) {
        int r = l / 236, c = l - r*236;
        float w;
        if (c < 59)       w = Wf[r*59 + c];
        else if (c < 177) w = Wc[r*118 + (c - 59)];
        else              w = Wi[r*59 + (c - 177)];
        s_wbig[r*237 + c] = w;
    }

    float acc[4] = {0.f, 0.f, 0.f, 0.f};
    for (int k0 = 0; k0 < 1024; k0 += 32) {
        for (int l = tid; l < 59*32; l += 256) {
            int r = l >> 5, kk = l & 31;
            s_w[r*33 + kk] = Wh[(size_t)r*1024 + k0 + kk];
        }
        for (int l = tid; l < 16*32; l += 256) {
            int r = l >> 5, kk = l & 31;
            int k = k0 + kk;
            int b = bBase + r;
            float hv = (k < 512)
                ? g_hf[((size_t)b*T_ + t)*H_ + k]
                : g_hb[((size_t)b*T_ + t)*H_ + (k - 512)];
            s_h[r*33 + kk] = hv;
        }
        __syncthreads();
        if (v < 59) {
            #pragma unroll
            for (int kk = 0; kk < 32; kk++) {
                float w = s_w[v*33 + kk];
                #pragma unroll
                for (int i = 0; i < 4; i++) acc[i] += w * s_h[(grp*4 + i)*33 + kk];
            }
        }
        __syncthreads();
    }
    if (v < 59) {
        float bias = bh[v];
        #pragma unroll
        for (int i = 0; i < 4; i++) s_xv[(grp*4 + i)*60 + v] = acc[i] + bias;
    }
    for (int l = tid; l < 16*59; l += 256) {
        int r = l / 59, kk = l - r*59;
        size_t g = ((size_t)(bBase + r)*T_ + t)*V_ + kk;
        s_val[r*60 + kk] = values[g];
        s_msk[r*60 + kk] = masks [g];
    }
    __syncthreads();

    if (v < 59) {
        float xh[4];
        float bias = bf[v] + bc[v];
        #pragma unroll
        for (int i = 0; i < 4; i++) xh[i] = bias;
        for (int k = 0; k < 59; k++) {
            float wf  = (k == v) ? 0.f : s_wbig[v*237 + k];
            float wc1 = s_wbig[v*237 + 59 + k];
            float wc2 = s_wbig[v*237 + 118 + k];
            #pragma unroll
            for (int i = 0; i < 4; i++) {
                int r = grp*4 + i;
                xh[i] += s_val[r*60 + k]*wf + s_xv[r*60 + k]*wc1 + s_msk[r*60 + k]*wc2;
            }
        }
        #pragma unroll
        for (int i = 0; i < 4; i++) s_xh[(grp*4 + i)*60 + v] = xh[i];
    }
    __syncthreads();

    float lnum = 0.f, lden = 0.f;
    if (v < 59) {
        #pragma unroll
        for (int i = 0; i < 4; i++) {
            int r = grp*4 + i;
            int b = bBase + r;
            float imp = bi[v];
            for (int k = 0; k < 59; k++) imp += s_xh[r*60 + k] * s_wbig[v*237 + 177 + k];
            float val = s_val[r*60 + v], m = s_msk[r*60 + v];
            out[((size_t)b*T_ + t)*V_ + v] = m*val + (1.f - m)*imp;
            lnum += fabsf(val - imp) * m;
            lden += m;
        }
    }
    s_red[tid] = lnum; __syncthreads();
    for (int st = 128; st > 0; st >>= 1) { if (tid < st) s_red[tid] += s_red[tid + st]; __syncthreads(); }
    if (tid == 0) atomicAdd(&g_num[t], s_red[0]);
    __syncthreads();
    s_red[tid] = lden; __syncthreads();
    for (int st = 128; st > 0; st >>= 1) { if (tid < st) s_red[tid] += s_red[tid + st]; __syncthreads(); }
    if (tid == 0) atomicAdd(&g_den[t], s_red[0]);
}

// ---------------- final loss reduction ----------------
__global__ void k_loss(float* __restrict__ out) {
    __shared__ float sr[128];
    int t = threadIdx.x;
    sr[t] = g_num[t] / (g_den[t] + 1e-5f);
    __syncthreads();
    for (int s = 64; s > 0; s >>= 1) { if (t < s) sr[t] += sr[t + s]; __syncthreads(); }
    if (t == 0) out[(size_t)B_*T_*V_] = sr[0];
}

// ---------------- launch ----------------
extern "C" void kernel_launch(void* const* d_in, const int* in_sizes, int n_in,
                              void* d_out, int out_size) {
    const float* values = (const float*)d_in[0];
    const float* masks  = (const float*)d_in[1];
    const float* df     = (const float*)d_in[2];
    const float* db     = (const float*)d_in[3];
    const float* Wih    = (const float*)d_in[4];
    const float* Whh    = (const float*)d_in[5];
    const float* bih    = (const float*)d_in[6];
    const float* bhh    = (const float*)d_in[7];
    const float* Wh     = (const float*)d_in[8];
    const float* bh     = (const float*)d_in[9];
    const float* Wf     = (const float*)d_in[10];
    const float* bf     = (const float*)d_in[11];
    const float* Wc     = (const float*)d_in[12];
    const float* bc     = (const float*)d_in[13];
    const float* Wi     = (const float*)d_in[14];
    const float* bi     = (const float*)d_in[15];
    float* out = (float*)d_out;

    cudaFuncSetAttribute(k_post, cudaFuncAttributeMaxDynamicSharedMemorySize,
                         P3_TOTAL * (int)sizeof(float));
    cudaFuncSetAttribute(k_gru_step, cudaFuncAttributeMaxDynamicSharedMemorySize,
                         STEP_SMEM);

    k_init<<<(B_*H_ + 255)/256, 256>>>();
    k_phase1<<<dim3(H3_/64, BT_/64), 256>>>(values, masks, df, db, Wih, bih);
    for (int s = 0; s < T_ - 1; s++)
        k_gru_step<<<dim3(8, 8, 2), 256, STEP_SMEM>>>(Whh, bhh, s);
    k_post<<<dim3(T_, B_/16), 256, P3_TOTAL * sizeof(float)>>>(
        values, masks, Wh, bh, Wf, bf, Wc, bc, Wi, bi, out);
    k_loss<<<1, 128>>>(out);
}

// round 11
// speedup vs baseline: 1.7161x; 1.2449x over previous
#include <cuda_runtime.h>
#include <math.h>

#define B_  512
#define T_  128
#define V_  59
#define H_  512
#define H3_ 1536
#define BT_ (B_*T_)

// ---------------- scratch (static __device__, no allocations) ----------------
__device__ float g_gif[(size_t)BT_*H3_];   // forward  gi (includes bih)
__device__ float g_gib[(size_t)BT_*H3_];   // backward gi (includes bih)
__device__ float g_hf [(size_t)BT_*H_];    // forward  pre-update hiddens
__device__ float g_hb [(size_t)BT_*H_];    // backward pre-update hiddens (time-aligned)
__device__ float g_num[T_];
__device__ float g_den[T_];

// ---------------- f32x2 helpers (Blackwell packed fp32) ----------------
typedef unsigned long long ull;
__device__ __forceinline__ ull pk2(float a, float b) {
    ull r; asm("mov.b64 %0, {%1, %2};" : "=l"(r) : "f"(a), "f"(b)); return r;
}
__device__ __forceinline__ void upk2(ull v, float& a, float& b) {
    asm("mov.b64 {%0, %1}, %2;" : "=f"(a), "=f"(b) : "l"(v));
}
__device__ __forceinline__ void fma2(ull& d, ull a, ull b) {
    asm("fma.rn.f32x2 %0, %1, %2, %3;" : "=l"(d) : "l"(a), "l"(b), "l"(d));
}

// ---------------- init: zero h0 states and loss accumulators ----------------
__global__ void k_init() {
    int idx = blockIdx.x * 256 + threadIdx.x;
    if (idx < B_*H_) {
        int b = idx >> 9, j = idx & 511;
        g_hf[(size_t)b*T_*H_ + j] = 0.f;                       // hf[b,0,:]   = 0
        g_hb[(size_t)b*T_*H_ + (size_t)(T_-1)*H_ + j] = 0.f;   // hb[b,T-1,:] = 0
    }
    if (idx < T_) { g_num[idx] = 0.f; g_den[idx] = 0.f; }
}

// ---------------- phase 1: fused gi GEMM for both directions ----------------
__global__ __launch_bounds__(256) void k_phase1(
    const float* __restrict__ values, const float* __restrict__ masks,
    const float* __restrict__ df,     const float* __restrict__ db,
    const float* __restrict__ Wih,    const float* __restrict__ bih)
{
    __shared__ float sx [64][33];
    __shared__ float sx2[64][33];
    __shared__ float sw [64][33];

    int tid = threadIdx.x;
    int tx = tid & 15, ty = tid >> 4;
    int rBase = blockIdx.y * 64;   // bt rows
    int cBase = blockIdx.x * 64;   // output cols (0..1535)

    float accA[4][4]; float accF[4][4]; float accB[4][4];
    #pragma unroll
    for (int i = 0; i < 4; i++)
        #pragma unroll
        for (int j = 0; j < 4; j++) { accA[i][j]=0.f; accF[i][j]=0.f; accB[i][j]=0.f; }

    // ---- part A: k in [0,118)  (values | masks), zero-padded ----
    for (int k0 = 0; k0 < 118; k0 += 32) {
        for (int l = tid; l < 64*32; l += 256) {
            int r = l >> 5, kk = l & 31;
            int k = k0 + kk;
            int bt = rBase + r;
            float xv = 0.f;
            if (k < 59)       xv = values[(size_t)bt*V_ + k];
            else if (k < 118) xv = masks [(size_t)bt*V_ + (k - 59)];
            sx[r][kk] = xv;
        }
        for (int l = tid; l < 64*32; l += 256) {
            int r = l >> 5, kk = l & 31;
            int k = k0 + kk;
            sw[r][kk] = (k < 118) ? Wih[(size_t)(cBase + r)*177 + k] : 0.f;
        }
        __syncthreads();
        #pragma unroll
        for (int kk = 0; kk < 32; kk++) {
            float xr[4], wr[4];
            #pragma unroll
            for (int i = 0; i < 4; i++) xr[i] = sx[ty + 16*i][kk];
            #pragma unroll
            for (int j = 0; j < 4; j++) wr[j] = sw[tx + 16*j][kk];
            #pragma unroll
            for (int i = 0; i < 4; i++)
                #pragma unroll
                for (int j = 0; j < 4; j++) accA[i][j] += xr[i]*wr[j];
        }
        __syncthreads();
    }

    // ---- part F/B: k in [0,59) against Wd = Wih[:,118:177] ----
    for (int k0 = 0; k0 < 59; k0 += 32) {
        for (int l = tid; l < 64*32; l += 256) {
            int r = l >> 5, kk = l & 31;
            int k = k0 + kk;
            int bt = rBase + r;
            int b = bt >> 7, t = bt & 127;
            int btf = (b << 7) + (127 - t);
            float fv = 0.f, bv = 0.f;
            if (k < 59) {
                fv = df[(size_t)bt *V_ + k];
                bv = db[(size_t)btf*V_ + k];
            }
            sx [r][kk] = fv;
            sx2[r][kk] = bv;
        }
        for (int l = tid; l < 64*32; l += 256) {
            int r = l >> 5, kk = l & 31;
            int k = k0 + kk;
            sw[r][kk] = (k < 59) ? Wih[(size_t)(cBase + r)*177 + 118 + k] : 0.f;
        }
        __syncthreads();
        #pragma unroll
        for (int kk = 0; kk < 32; kk++) {
            float fr[4], br[4], wr[4];
            #pragma unroll
            for (int i = 0; i < 4; i++) { fr[i] = sx[ty+16*i][kk]; br[i] = sx2[ty+16*i][kk]; }
            #pragma unroll
            for (int j = 0; j < 4; j++) wr[j] = sw[tx + 16*j][kk];
            #pragma unroll
            for (int i = 0; i < 4; i++)
                #pragma unroll
                for (int j = 0; j < 4; j++) {
                    accF[i][j] += fr[i]*wr[j];
                    accB[i][j] += br[i]*wr[j];
                }
        }
        __syncthreads();
    }

    // ---- write: gif[bt,c] and gib[b, T-1-t, c] ----
    #pragma unroll
    for (int j = 0; j < 4; j++) {
        int c = cBase + tx + 16*j;
        float bias = bih[c];
        #pragma unroll
        for (int i = 0; i < 4; i++) {
            int bt = rBase + ty + 16*i;
            int b = bt >> 7, t = bt & 127;
            int btf = (b << 7) + (127 - t);
            g_gif[(size_t)bt *H3_ + c] = accA[i][j] + accF[i][j] + bias;
            g_gib[(size_t)btf*H3_ + c] = accA[i][j] + accB[i][j] + bias;
        }
    }
}

// ---------------- phase 2: one recurrence step, both directions ----------------
// grid (8 jblk, 8 bblk, 2 dir). CTA: 512 threads, tile 64 b x 64 j x 3 gates, K=512.
// 16 warps (4 per SMSP) for latency hiding. FFMA2 mainloop, double-buffered smem.
// smem per buffer:
//   h tile: [64][36]  (row-major, 16B-aligned rows for LDS.128 over 4 kk)
//   w tile: 3 x [32][66] transposed (row=kk, col=j) for LDS.64 packed operands
#define SP_H   36
#define SP_W   66
#define HBF    (64*SP_H)                 // 2304
#define WBF    (32*SP_W)                 // 2112
#define BUF_F  (HBF + 3*WBF)             // 8640 floats per buffer
#define STEP_SMEM (2*BUF_F*(int)sizeof(float))

__global__ __launch_bounds__(512) void k_gru_step(
    const float* __restrict__ Whh, const float* __restrict__ bhh, int s)
{
    extern __shared__ float smem[];

    int dir = blockIdx.z;
    const float* gi = dir ? g_gib : g_gif;
    float* hbuf     = dir ? g_hb  : g_hf;
    int t_in  = dir ? (127 - s) : s;
    int t_out = dir ? (126 - s) : (s + 1);

    int tid = threadIdx.x;
    int tx = tid & 31;          // 32 lanes -> 64 cols (2 per lane, packed)
    int ty = tid >> 5;          // 16 warps -> 64 rows (4 per thread, stride 16)
    int bBase = blockIdx.y * 64;
    int jBase = blockIdx.x * 64;

    // accumulators: [gate][i], each ull = 2 adjacent output cols
    ull acc[3][4];
    #pragma unroll
    for (int g = 0; g < 3; g++)
        #pragma unroll
        for (int i = 0; i < 4; i++) acc[g][i] = 0ull;

    // cooperative-load indices: one float4 of h, three float4 of w per thread
    int lr = tid >> 3, lq = tid & 7;

    const float* hsrc = &hbuf[((size_t)(bBase + lr)*T_ + t_in)*H_ + lq*4];

    // ---- prologue: tile 0 -> buffer 0 ----
    {
        float4 ph = *reinterpret_cast<const float4*>(hsrc);
        float4 pw[3];
        #pragma unroll
        for (int g = 0; g < 3; g++)
            pw[g] = *reinterpret_cast<const float4*>(
                &Whh[(size_t)(g*H_ + jBase + lr)*H_ + lq*4]);

        float* bh = smem;
        *reinterpret_cast<float4*>(&bh[lr*SP_H + lq*4]) = ph;
        #pragma unroll
        for (int g = 0; g < 3; g++) {
            float* bw = smem + HBF + g*WBF;
            bw[(lq*4+0)*SP_W + lr] = pw[g].x;
            bw[(lq*4+1)*SP_W + lr] = pw[g].y;
            bw[(lq*4+2)*SP_W + lr] = pw[g].z;
            bw[(lq*4+3)*SP_W + lr] = pw[g].w;
        }
    }
    __syncthreads();

    // ---- mainloop over 16 k-tiles ----
    for (int kt = 0; kt < 16; kt++) {
        int cur = kt & 1;
        float* buf = smem + cur*BUF_F;

        float4 ph, pw[3];
        if (kt < 15) {
            int k0 = (kt + 1) * 32;
            ph = *reinterpret_cast<const float4*>(hsrc + k0);
            #pragma unroll
            for (int g = 0; g < 3; g++)
                pw[g] = *reinterpret_cast<const float4*>(
                    &Whh[(size_t)(g*H_ + jBase + lr)*H_ + k0 + lq*4]);
        }

        const float* bh  = buf;
        const float* bw0 = buf + HBF;
        const float* bw1 = buf + HBF + WBF;
        const float* bw2 = buf + HBF + 2*WBF;
        #pragma unroll
        for (int k4 = 0; k4 < 8; k4++) {
            // h for 4 kk at once, broadcast across tx (uniform address per warp)
            float4 h4[4];
            #pragma unroll
            for (int i = 0; i < 4; i++)
                h4[i] = *reinterpret_cast<const float4*>(
                    &bh[(ty + 16*i)*SP_H + k4*4]);
            #pragma unroll
            for (int c = 0; c < 4; c++) {
                int kk = k4*4 + c;
                ull w0 = *reinterpret_cast<const ull*>(&bw0[kk*SP_W + 2*tx]);
                ull w1 = *reinterpret_cast<const ull*>(&bw1[kk*SP_W + 2*tx]);
                ull w2 = *reinterpret_cast<const ull*>(&bw2[kk*SP_W + 2*tx]);
                #pragma unroll
                for (int i = 0; i < 4; i++) {
                    float hv = (c == 0) ? h4[i].x : (c == 1) ? h4[i].y
                             : (c == 2) ? h4[i].z : h4[i].w;
                    ull h2 = pk2(hv, hv);
                    fma2(acc[0][i], h2, w0);
                    fma2(acc[1][i], h2, w1);
                    fma2(acc[2][i], h2, w2);
                }
            }
        }

        if (kt < 15) {
            float* nbuf = smem + (1 - cur)*BUF_F;
            *reinterpret_cast<float4*>(&nbuf[lr*SP_H + lq*4]) = ph;
            #pragma unroll
            for (int g = 0; g < 3; g++) {
                float* bwn = nbuf + HBF + g*WBF;
                bwn[(lq*4+0)*SP_W + lr] = pw[g].x;
                bwn[(lq*4+1)*SP_W + lr] = pw[g].y;
                bwn[(lq*4+2)*SP_W + lr] = pw[g].z;
                bwn[(lq*4+3)*SP_W + lr] = pw[g].w;
            }
        }
        __syncthreads();
    }

    // ---- gate epilogue: each thread finishes 4 rows x 2 cols ----
    int jj = jBase + 2*tx;
    float2 bhr = *reinterpret_cast<const float2*>(&bhh[jj]);
    float2 bhz = *reinterpret_cast<const float2*>(&bhh[H_  + jj]);
    float2 bhn = *reinterpret_cast<const float2*>(&bhh[2*H_ + jj]);
    #pragma unroll
    for (int i = 0; i < 4; i++) {
        int b = bBase + ty + 16*i;
        const float* girow = &gi[((size_t)b*T_ + s)*H3_];
        float2 gir = *reinterpret_cast<const float2*>(&girow[jj]);
        float2 giz = *reinterpret_cast<const float2*>(&girow[H_  + jj]);
        float2 gin = *reinterpret_cast<const float2*>(&girow[2*H_ + jj]);
        float2 hp  = *reinterpret_cast<const float2*>(
            &hbuf[((size_t)b*T_ + t_in)*H_ + jj]);

        float ar[2], az[2], an[2];
        upk2(acc[0][i], ar[0], ar[1]);
        upk2(acc[1][i], az[0], az[1]);
        upk2(acc[2][i], an[0], an[1]);

        float2 ho;
        {
            float r = 1.f / (1.f + __expf(-(gir.x + ar[0] + bhr.x)));
            float z = 1.f / (1.f + __expf(-(giz.x + az[0] + bhz.x)));
            float n = tanhf(gin.x + r*(an[0] + bhn.x));
            ho.x = (1.f - z)*n + z*hp.x;
        }
        {
            float r = 1.f / (1.f + __expf(-(gir.y + ar[1] + bhr.y)));
            float z = 1.f / (1.f + __expf(-(giz.y + az[1] + bhz.y)));
            float n = tanhf(gin.y + r*(an[1] + bhn.y));
            ho.y = (1.f - z)*n + z*hp.y;
        }
        *reinterpret_cast<float2*>(&hbuf[((size_t)b*T_ + t_out)*H_ + jj]) = ho;
    }
}

// ---------------- phase 3: fused regression chain + loss ----------------
#define P3_WBIG  0                       // [59][237]  Wf|Wc|Wi rows
#define P3_W     (P3_WBIG + 59*237)      // [59][33]   Wh k-tile
#define P3_H     (P3_W    + 59*33)       // [16][33]   h2 k-tile
#define P3_XV    (P3_H    + 16*33)       // [16][60]
#define P3_VAL   (P3_XV   + 16*60)
#define P3_MSK   (P3_VAL  + 16*60)
#define P3_XH    (P3_MSK  + 16*60)
#define P3_RED   (P3_XH   + 16*60)       // [256]
#define P3_TOTAL (P3_RED  + 256)         // floats

__global__ __launch_bounds__(256) void k_post(
    const float* __restrict__ values, const float* __restrict__ masks,
    const float* __restrict__ Wh, const float* __restrict__ bh,
    const float* __restrict__ Wf, const float* __restrict__ bf,
    const float* __restrict__ Wc, const float* __restrict__ bc,
    const float* __restrict__ Wi, const float* __restrict__ bi,
    float* __restrict__ out)
{
    extern __shared__ float smem[];
    float* s_wbig = smem + P3_WBIG;
    float* s_w    = smem + P3_W;
    float* s_h    = smem + P3_H;
    float* s_xv   = smem + P3_XV;
    float* s_val  = smem + P3_VAL;
    float* s_msk  = smem + P3_MSK;
    float* s_xh   = smem + P3_XH;
    float* s_red  = smem + P3_RED;

    int t = blockIdx.x;
    int bBase = blockIdx.y * 16;
    int tid = threadIdx.x;
    int v   = tid & 63;
    int grp = tid >> 6;

    for (int l = tid; l < 59*236; l += 256) {
        int r = l / 236, c = l - r*236;
        float w;
        if (c < 59)       w = Wf[r*59 + c];
        else if (c < 177) w = Wc[r*118 + (c - 59)];
        else              w = Wi[r*59 + (c - 177)];
        s_wbig[r*237 + c] = w;
    }

    float acc[4] = {0.f, 0.f, 0.f, 0.f};
    for (int k0 = 0; k0 < 1024; k0 += 32) {
        for (int l = tid; l < 59*32; l += 256) {
            int r = l >> 5, kk = l & 31;
            s_w[r*33 + kk] = Wh[(size_t)r*1024 + k0 + kk];
        }
        for (int l = tid; l < 16*32; l += 256) {
            int r = l >> 5, kk = l & 31;
            int k = k0 + kk;
            int b = bBase + r;
            float hv = (k < 512)
                ? g_hf[((size_t)b*T_ + t)*H_ + k]
                : g_hb[((size_t)b*T_ + t)*H_ + (k - 512)];
            s_h[r*33 + kk] = hv;
        }
        __syncthreads();
        if (v < 59) {
            #pragma unroll
            for (int kk = 0; kk < 32; kk++) {
                float w = s_w[v*33 + kk];
                #pragma unroll
                for (int i = 0; i < 4; i++) acc[i] += w * s_h[(grp*4 + i)*33 + kk];
            }
        }
        __syncthreads();
    }
    if (v < 59) {
        float bias = bh[v];
        #pragma unroll
        for (int i = 0; i < 4; i++) s_xv[(grp*4 + i)*60 + v] = acc[i] + bias;
    }
    for (int l = tid; l < 16*59; l += 256) {
        int r = l / 59, kk = l - r*59;
        size_t g = ((size_t)(bBase + r)*T_ + t)*V_ + kk;
        s_val[r*60 + kk] = values[g];
        s_msk[r*60 + kk] = masks [g];
    }
    __syncthreads();

    if (v < 59) {
        float xh[4];
        float bias = bf[v] + bc[v];
        #pragma unroll
        for (int i = 0; i < 4; i++) xh[i] = bias;
        for (int k = 0; k < 59; k++) {
            float wf  = (k == v) ? 0.f : s_wbig[v*237 + k];
            float wc1 = s_wbig[v*237 + 59 + k];
            float wc2 = s_wbig[v*237 + 118 + k];
            #pragma unroll
            for (int i = 0; i < 4; i++) {
                int r = grp*4 + i;
                xh[i] += s_val[r*60 + k]*wf + s_xv[r*60 + k]*wc1 + s_msk[r*60 + k]*wc2;
            }
        }
        #pragma unroll
        for (int i = 0; i < 4; i++) s_xh[(grp*4 + i)*60 + v] = xh[i];
    }
    __syncthreads();

    float lnum = 0.f, lden = 0.f;
    if (v < 59) {
        #pragma unroll
        for (int i = 0; i < 4; i++) {
            int r = grp*4 + i;
            int b = bBase + r;
            float imp = bi[v];
            for (int k = 0; k < 59; k++) imp += s_xh[r*60 + k] * s_wbig[v*237 + 177 + k];
            float val = s_val[r*60 + v], m = s_msk[r*60 + v];
            out[((size_t)b*T_ + t)*V_ + v] = m*val + (1.f - m)*imp;
            lnum += fabsf(val - imp) * m;
            lden += m;
        }
    }
    s_red[tid] = lnum; __syncthreads();
    for (int st = 128; st > 0; st >>= 1) { if (tid < st) s_red[tid] += s_red[tid + st]; __syncthreads(); }
    if (tid == 0) atomicAdd(&g_num[t], s_red[0]);
    __syncthreads();
    s_red[tid] = lden; __syncthreads();
    for (int st = 128; st > 0; st >>= 1) { if (tid < st) s_red[tid] += s_red[tid + st]; __syncthreads(); }
    if (tid == 0) atomicAdd(&g_den[t], s_red[0]);
}

// ---------------- final loss reduction ----------------
__global__ void k_loss(float* __restrict__ out) {
    __shared__ float sr[128];
    int t = threadIdx.x;
    sr[t] = g_num[t] / (g_den[t] + 1e-5f);
    __syncthreads();
    for (int s = 64; s > 0; s >>= 1) { if (t < s) sr[t] += sr[t + s]; __syncthreads(); }
    if (t == 0) out[(size_t)B_*T_*V_] = sr[0];
}

// ---------------- launch ----------------
extern "C" void kernel_launch(void* const* d_in, const int* in_sizes, int n_in,
                              void* d_out, int out_size) {
    const float* values = (const float*)d_in[0];
    const float* masks  = (const float*)d_in[1];
    const float* df     = (const float*)d_in[2];
    const float* db     = (const float*)d_in[3];
    const float* Wih    = (const float*)d_in[4];
    const float* Whh    = (const float*)d_in[5];
    const float* bih    = (const float*)d_in[6];
    const float* bhh    = (const float*)d_in[7];
    const float* Wh     = (const float*)d_in[8];
    const float* bh     = (const float*)d_in[9];
    const float* Wf     = (const float*)d_in[10];
    const float* bf     = (const float*)d_in[11];
    const float* Wc     = (const float*)d_in[12];
    const float* bc     = (const float*)d_in[13];
    const float* Wi     = (const float*)d_in[14];
    const float* bi     = (const float*)d_in[15];
    float* out = (float*)d_out;

    cudaFuncSetAttribute(k_post, cudaFuncAttributeMaxDynamicSharedMemorySize,
                         P3_TOTAL * (int)sizeof(float));
    cudaFuncSetAttribute(k_gru_step, cudaFuncAttributeMaxDynamicSharedMemorySize,
                         STEP_SMEM);

    k_init<<<(B_*H_ + 255)/256, 256>>>();
    k_phase1<<<dim3(H3_/64, BT_/64), 256>>>(values, masks, df, db, Wih, bih);
    for (int s = 0; s < T_ - 1; s++)
        k_gru_step<<<dim3(8, 8, 2), 512, STEP_SMEM>>>(Whh, bhh, s);
    k_post<<<dim3(T_, B_/16), 256, P3_TOTAL * sizeof(float)>>>(
        values, masks, Wh, bh, Wf, bf, Wc, bc, Wi, bi, out);
    k_loss<<<1, 128>>>(out);
}